// round 1
// baseline (speedup 1.0000x reference)
#include <cuda_runtime.h>
#include <cstdint>

// Unfold (im2col) disguised as depthwise conv with identity kernel.
// x: [16, 64, 112, 112] f32 ; out: [16, 576, 112, 112] f32
// out[n, c*9+kk, h, w] = x[n, c, h + kk/3 - 1, w + kk%3 - 1] (0 outside)
//
// Pure data movement: ~462 MB stores + ~51 MB input (L2-resident across the
// 9x reuse). One thread = 4 consecutive output pixels along W (float4 store,
// perfectly aligned since W=112). Output linear index == 4 * global tid.

#define N_    16
#define C_    64
#define HW_   112
#define KKN   9
#define WQ    28   // 112 / 4

__global__ __launch_bounds__(256) void unfold_kernel(
    const float* __restrict__ x, float* __restrict__ out)
{
    const int total = N_ * C_ * KKN * HW_ * WQ;  // 28,901,376
    int idx = blockIdx.x * blockDim.x + threadIdx.x;
    if (idx >= total) return;

    int t  = idx;
    int wq = t % WQ;  t /= WQ;
    int h  = t % HW_; t /= HW_;
    int kk = t % KKN; t /= KKN;
    int c  = t % C_;
    int n  = t / C_;

    const int kh = kk / 3 - 1;      // -1, 0, 1
    const int kw = kk % 3 - 1;      // -1, 0, 1
    const int ih = h + kh;
    const int w0 = wq * 4;

    float4 v = make_float4(0.f, 0.f, 0.f, 0.f);

    if (ih >= 0 && ih < HW_) {
        const float* row = x + (((int64_t)(n * C_ + c)) * HW_ + ih) * HW_;
        int iw0 = w0 + kw;
        // interior fast path: all 4 reads in range
        if (iw0 >= 0 && iw0 + 3 < HW_) {
            v.x = row[iw0];
            v.y = row[iw0 + 1];
            v.z = row[iw0 + 2];
            v.w = row[iw0 + 3];
        } else {
            float tmp[4];
            #pragma unroll
            for (int i = 0; i < 4; ++i) {
                int iw = iw0 + i;
                tmp[i] = (iw >= 0 && iw < HW_) ? row[iw] : 0.f;
            }
            v.x = tmp[0]; v.y = tmp[1]; v.z = tmp[2]; v.w = tmp[3];
        }
    }

    reinterpret_cast<float4*>(out)[idx] = v;
}

extern "C" void kernel_launch(void* const* d_in, const int* in_sizes, int n_in,
                              void* d_out, int out_size)
{
    const float* x = (const float*)d_in[0];
    // d_in[1] is the identity weight; unused by construction.
    float* out = (float*)d_out;

    const int total = N_ * C_ * KKN * HW_ * WQ;
    const int threads = 256;
    const int blocks = (total + threads - 1) / threads;
    unfold_kernel<<<blocks, threads>>>(x, out);
}

// round 2
// speedup vs baseline: 1.5352x; 1.5352x over previous
#include <cuda_runtime.h>
#include <cstdint>

// Unfold (im2col) as warp-per-row shuffle kernel.
// x: [16, 64, 112, 112] f32 ; out: [16, 576, 112, 112] f32
// out[n, c*9 + kh*3 + kw, h, w] = x[n, c, h+kh-1, w+kw-1] (0 outside)
//
// One warp per (n,c,h). Lanes 0..27 each own 4 consecutive w (float4).
// Load rows h-1,h,h+1 as aligned float4 (3 LDG.128), build the kw=-1/+1
// shifted vectors with __shfl of neighbor lanes, emit 9 aligned STG.128.
// Lanes 28..31 carry zeros -> shfl_down across lane 27 naturally yields the
// right-edge padding zero.

#define HWDIM 112
#define PLANE (HWDIM * HWDIM)   // 12544

__global__ __launch_bounds__(256) void unfold_kernel(
    const float* __restrict__ x, float* __restrict__ out)
{
    const int warp = (blockIdx.x * blockDim.x + threadIdx.x) >> 5;
    const int lane = threadIdx.x & 31;

    // warp -> (n, c, h); grid launched exactly: 16*64*112 warps
    int h = warp % HWDIM;
    int t = warp / HWDIM;
    int c = t & 63;          // % 64
    int n = t >> 6;          // / 64

    const bool wok = lane < 28;
    const int w0 = lane * 4;

    const float* plane = x + (int64_t)(n * 64 + c) * PLANE;

    float4 r[3];
#pragma unroll
    for (int i = 0; i < 3; ++i) {
        const int ih = h + i - 1;
        if (wok && (unsigned)ih < HWDIM)
            r[i] = *reinterpret_cast<const float4*>(plane + ih * HWDIM + w0);
        else
            r[i] = make_float4(0.f, 0.f, 0.f, 0.f);
    }

    float* obase = out + ((int64_t)(n * 576 + c * 9) * HWDIM + h) * HWDIM + w0;

#pragma unroll
    for (int i = 0; i < 3; ++i) {
        const float4 cur = r[i];
        float pw = __shfl_up_sync(0xFFFFFFFFu, cur.w, 1);   // prev lane's .w
        if (lane == 0) pw = 0.f;                            // left-edge pad
        float nx = __shfl_down_sync(0xFFFFFFFFu, cur.x, 1); // next lane's .x
        // lane 27 receives lane 28's zero -> right-edge pad automatically

        const float4 vm = make_float4(pw, cur.x, cur.y, cur.z);   // kw = -1
        const float4 vp = make_float4(cur.y, cur.z, cur.w, nx);   // kw = +1

        if (wok) {
            *reinterpret_cast<float4*>(obase + (int64_t)(i * 3 + 0) * PLANE) = vm;
            *reinterpret_cast<float4*>(obase + (int64_t)(i * 3 + 1) * PLANE) = cur;
            *reinterpret_cast<float4*>(obase + (int64_t)(i * 3 + 2) * PLANE) = vp;
        }
    }
}

extern "C" void kernel_launch(void* const* d_in, const int* in_sizes, int n_in,
                              void* d_out, int out_size)
{
    const float* x = (const float*)d_in[0];
    float* out = (float*)d_out;

    const int warps = 16 * 64 * HWDIM;        // 114688
    const int threads = 256;                  // 8 warps/block
    const int blocks = warps / 8;             // 14336, exact
    unfold_kernel<<<blocks, threads>>>(x, out);
}